// round 2
// baseline (speedup 1.0000x reference)
#include <cuda_runtime.h>
#include <cuda_fp16.h>

// ContrastHead: neighbor-contrastive loss.
//   N=200000 points, K=16 neighbors, C=32 features, T=0.1, weight=0.1, eps=1e-8
// Inputs: features f32 [N*C], labels i32 [N], neighbor_idx [N*K] (int32 or int64, runtime-detect)
// Output: 1 float.
//
// Strategy: convert features to fp16 (halves the L2 gather traffic, the dominant cost),
// warp-per-point main kernel with 4-lane-group gathers, per-block partials (no atomics),
// 1-block finalize. Quantization error on the final mean: ~1e-5, gate is 1e-3.

#define KNB 16
#define CF  32
#define NMAX 200064
#define MAXBLK 32768

__device__ __align__(16) uint4 g_feat16[NMAX * 4];   // N rows of 32 halfs = 4 uint4 per row
__device__ float2 g_part[MAXBLK];

// f32 -> f16 conversion: each thread converts 8 floats -> 1 uint4 of half2s.
__global__ __launch_bounds__(256) void ch_convert_kernel(
    const float4* __restrict__ feat, int tot8)
{
    int i = blockIdx.x * blockDim.x + threadIdx.x;
    if (i >= tot8) return;
    float4 a = feat[2 * i];
    float4 b = feat[2 * i + 1];
    __half2 h0 = __floats2half2_rn(a.x, a.y);
    __half2 h1 = __floats2half2_rn(a.z, a.w);
    __half2 h2 = __floats2half2_rn(b.x, b.y);
    __half2 h3 = __floats2half2_rn(b.z, b.w);
    uint4 o;
    o.x = *reinterpret_cast<unsigned*>(&h0);
    o.y = *reinterpret_cast<unsigned*>(&h1);
    o.z = *reinterpret_cast<unsigned*>(&h2);
    o.w = *reinterpret_cast<unsigned*>(&h3);
    g_feat16[i] = o;
}

__device__ __forceinline__ float dist8(uint4 c, uint4 nf) {
    float sum = 0.0f;
    const __half2* ch = reinterpret_cast<const __half2*>(&c);
    const __half2* nh = reinterpret_cast<const __half2*>(&nf);
#pragma unroll
    for (int q = 0; q < 4; q++) {
        float2 fc = __half22float2(ch[q]);
        float2 fn = __half22float2(nh[q]);
        float d0 = fc.x - fn.x;
        float d1 = fc.y - fn.y;
        sum = fmaf(d0, d0, sum);
        sum = fmaf(d1, d1, sum);
    }
    return sum;
}

__global__ __launch_bounds__(256) void ch_main_kernel(
    const int*  __restrict__ labels,
    const void* __restrict__ nbr,
    int n)
{
    const unsigned FULL = 0xffffffffu;
    const int lane = threadIdx.x & 31;
    const int wid  = threadIdx.x >> 5;
    const int wp   = (blockIdx.x * blockDim.x + threadIdx.x) >> 5;   // warp -> point
    const bool active = (wp < n);
    const int p = active ? wp : 0;

    // dtype detect: if int64, odd 32-bit words of the first 16 neighbor entries are all 0.
    // One broadcast 128B line per warp; P(false positive for int32) ~ (1/N)^16.
    int probe = 1;
    if (lane < KNB) probe = reinterpret_cast<const int*>(nbr)[2 * lane + 1];
    const unsigned zballot = __ballot_sync(FULL, probe == 0);
    const bool is64 = ((zballot & 0xFFFFu) == 0xFFFFu);

    const int lab = labels[p];

    // 4-lane groups: lane's chunk of any 64B row is (lane&3)
    const uint4 cc = g_feat16[(size_t)p * 4 + (lane & 3)];

    int myidx = 0;
    if (lane < KNB) {
        if (is64)
            myidx = (int)reinterpret_cast<const long long*>(nbr)[(size_t)p * KNB + lane];
        else
            myidx = reinterpret_cast<const int*>(nbr)[(size_t)p * KNB + lane];
    }
    const int nblab = labels[(lane < KNB) ? myidx : 0];

    // 2 iterations x 8 neighbors: group g = lane>>2 handles neighbor t*8+g
    float dist2 = 0.0f;
#pragma unroll
    for (int t = 0; t < 2; t++) {
        const int src = t * 8 + (lane >> 2);
        const int idx = __shfl_sync(FULL, myidx, src);
        const uint4 nf = g_feat16[(size_t)idx * 4 + (lane & 3)];
        float sum = dist8(cc, nf);
        sum += __shfl_xor_sync(FULL, sum, 2);
        sum += __shfl_xor_sync(FULL, sum, 1);
        // group (lane&7)'s total lives at lane 4*(lane&7); route to owner lane t*8+(lane&7)
        const float cand = __shfl_sync(FULL, sum, (lane & 7) << 2);
        if ((lane >> 3) == t) dist2 = cand;
    }

    const float nd = (lane < KNB) ? -sqrtf(dist2 + 1e-8f) : -1e30f;

    float m = nd;
    m = fmaxf(m, __shfl_xor_sync(FULL, m, 8));
    m = fmaxf(m, __shfl_xor_sync(FULL, m, 4));
    m = fmaxf(m, __shfl_xor_sync(FULL, m, 2));
    m = fmaxf(m, __shfl_xor_sync(FULL, m, 1));

    const float e = (lane < KNB) ? __expf((nd - m) * 10.0f) : 0.0f;   // 1/T = 10
    const float isp = (lane < KNB && nblab == lab) ? 1.0f : 0.0f;
    float pos = e * isp;
    float neg = e;
    float cnt = isp;
#pragma unroll
    for (int off = 8; off >= 1; off >>= 1) {
        pos += __shfl_xor_sync(FULL, pos, off);
        neg += __shfl_xor_sync(FULL, neg, off);
        cnt += __shfl_xor_sync(FULL, cnt, off);
    }

    __shared__ float s_num[8];
    __shared__ float s_den[8];
    if (lane == 0) {
        const float pm = (active && cnt > 0.5f && cnt < (float)KNB - 0.5f) ? 1.0f : 0.0f;
        const float loss = -__logf(pos / neg + 1e-8f);
        s_num[wid] = loss * pm;
        s_den[wid] = pm;
    }
    __syncthreads();
    if (threadIdx.x == 0) {
        float a = 0.0f, b = 0.0f;
#pragma unroll
        for (int i = 0; i < 8; i++) { a += s_num[i]; b += s_den[i]; }
        g_part[blockIdx.x] = make_float2(a, b);
    }
}

__global__ __launch_bounds__(1024) void ch_finalize_kernel(
    float* __restrict__ out, int nblocks)
{
    const unsigned FULL = 0xffffffffu;
    float a = 0.0f, b = 0.0f;
    for (int i = threadIdx.x; i < nblocks; i += 1024) {
        float2 v = g_part[i];
        a += v.x; b += v.y;
    }
#pragma unroll
    for (int off = 16; off >= 1; off >>= 1) {
        a += __shfl_xor_sync(FULL, a, off);
        b += __shfl_xor_sync(FULL, b, off);
    }
    __shared__ float sa[32], sb[32];
    if ((threadIdx.x & 31) == 0) { sa[threadIdx.x >> 5] = a; sb[threadIdx.x >> 5] = b; }
    __syncthreads();
    if (threadIdx.x == 0) {
        double na = 0.0, nb = 0.0;
#pragma unroll
        for (int i = 0; i < 32; i++) { na += sa[i]; nb += sb[i]; }
        if (nb < 1.0) nb = 1.0;
        out[0] = (float)(na / nb * 0.1);   // WEIGHT = 0.1
    }
}

extern "C" void kernel_launch(void* const* d_in, const int* in_sizes, int n_in,
                              void* d_out, int out_size) {
    const float* feat   = (const float*)d_in[0];
    const int*   labels = (const int*)d_in[1];
    const void*  nbr    = (const void*)d_in[2];
    float* out = (float*)d_out;
    (void)n_in; (void)out_size;

    const int n = in_sizes[1];                 // N points
    const int tot8 = n * (CF / 8);             // groups of 8 floats
    ch_convert_kernel<<<(tot8 + 255) / 256, 256>>>((const float4*)feat, tot8);

    const int blocks = (n + 7) / 8;            // 8 warps/block, warp per point
    ch_main_kernel<<<blocks, 256>>>(labels, nbr, n);

    ch_finalize_kernel<<<1, 1024>>>(out, blocks);
}